// round 6
// baseline (speedup 1.0000x reference)
#include <cuda_runtime.h>
#include <math.h>

#define B_ 32
#define C_ 128
#define N_ 307
#define TL 12
#define TH 13
#define TMAX 13
#define LAYERS 4
#define BN_EPS 1e-5f
#define E4 921            // float4 per (b,c) row  (307*12/4)
#define EF 3684           // floats per (b,c) row
#define NBLOCKS 512
#define NCHAIN 64
#define PADC 132

// ---------------- scratch (static __device__, no allocations) ----------------
__device__ float g_Gpart[8*2*4*B_*EF];           // (cb,ch,layer,b,e) 30.2 MB
__device__ float g_H [2*4*B_*TMAX*C_];           // (ch,layer,b,sl,c)
__device__ float g_GWpart[2*2*4*B_*TMAX*C_];     // (half,ch,layer,b,sl,c)
__device__ float g_logits[2][2*B_*TMAX*TMAX];    // double buffered per layer parity
__device__ float g_avec[2*B_*TMAX];              // final A column per (ch,b)
__device__ unsigned g_barA_count, g_barA_gen;    // all-512 barrier
__device__ unsigned g_bar64_count, g_bar64_gen;  // chain-block barrier
__device__ unsigned g_done_gen;                  // chain-done generation flag

__device__ __forceinline__ int GPidx(int cb,int ch,int i,int b){
    return (((cb*2+ch)*4+i)*B_+b)*EF;
}
__device__ __forceinline__ int Hidx(int ch,int i,int b,int s,int c){
    return (((ch*4+i)*B_+b)*TMAX+s)*C_+c;
}
__device__ __forceinline__ int GWPidx(int half,int ch,int i,int b){
    return (((half*2+ch)*4+i)*B_+b)*TMAX*C_;
}

__device__ __forceinline__ void barrier_n(unsigned* cnt, unsigned* gen, unsigned n, bool sleep){
    __threadfence();
    __syncthreads();
    if (threadIdx.x == 0){
        volatile unsigned* genp = (volatile unsigned*)gen;
        unsigned g = *genp;
        if (atomicAdd(cnt, 1u) == n - 1u){
            atomicExch(cnt, 0u);
            __threadfence();
            *genp = g + 1u;
        } else {
            if (sleep){ while (*genp == g) __nanosleep(32); }
            else      { while (*genp == g) {} }
        }
    }
    __syncthreads();
}

struct SMa { float ss[16][396]; float4 sc2[N_]; float4 sc1h[16]; };
struct SMb { float sg[1856]; float red[1536]; };
struct SMc { float A[TMAX*TMAX], A2[TMAX*TMAX];
             float GWs[TMAX*PADC], Hs[TMAX*PADC], f1w[TMAX*PADC], f2s[TMAX*PADC];
             float sS[TMAX*TMAX], slog[TMAX*TMAX], mu[TMAX], isd[TMAX]; };
struct SMd { float av[2*B_*TMAX]; };
union SMU { SMa a; SMb b; SMc c; SMd d; };

// ---- phase A chunk, compile-time NN (32 main / 19 tail) ---------------------
template<int NN>
__device__ __forceinline__ void chunkA(
    SMU& sm, const float4* __restrict__ X4, size_t xbase, int nk,
    int tid, int cl, int s12, bool act,
    float& h0, float& h1, float& h2, float& h3,
    float* __restrict__ g0p, float* __restrict__ g1p,
    float* __restrict__ g2p, float* __restrict__ g3p)
{
    __syncthreads();
    #pragma unroll
    for (int j0 = 0; j0 < 1536; j0 += 256){
        int j = j0 + tid;
        int c = j / 96, r = j - c*96;        // compile-time divisor
        if (r < NN*3)
            *(float4*)&sm.a.ss[c][r*4] = X4[xbase + (size_t)c*E4 + nk*96 + r];
    }
    __syncthreads();
    if (act){
        const float4* s2 = &sm.a.sc2[nk*32];
        #pragma unroll
        for (int nl = 0; nl < NN; nl++){
            float  v = sm.a.ss[cl][nl*12 + s12];
            float4 w = s2[nl];
            h0 = fmaf(w.x, v, h0);
            h1 = fmaf(w.y, v, h1);
            h2 = fmaf(w.z, v, h2);
            h3 = fmaf(w.w, v, h3);
        }
    }
    #pragma unroll
    for (int j0 = 0; j0 < NN*12; j0 += 256){
        int j = j0 + tid;
        if (j < NN*12){
            int nl = j / 12, sg_ = j - nl*12;
            float p0=0.f, p1=0.f, p2=0.f, p3=0.f;
            #pragma unroll
            for (int cc = 0; cc < 16; cc++){
                float  v = sm.a.ss[cc][nl*12 + sg_];
                float4 w = sm.a.sc1h[cc];
                p0 = fmaf(w.x, v, p0);
                p1 = fmaf(w.y, v, p1);
                p2 = fmaf(w.z, v, p2);
                p3 = fmaf(w.w, v, p3);
            }
            int e = nk*384 + j;
            __stcs(&g0p[e], p0);      // streaming: read-once scratch, don't evict X
            __stcs(&g1p[e], p1);
            __stcs(&g2p[e], p2);
            __stcs(&g3p[e], p3);
        }
    }
}

__global__ void __launch_bounds__(256, 4) mega_kernel(
    const float* __restrict__ XL,  const float* __restrict__ XH,
    const float* __restrict__ c1L, const float* __restrict__ c2L,
    const float* __restrict__ wL,  const float* __restrict__ bL,
    const float* __restrict__ vL,  const float* __restrict__ gL,
    const float* __restrict__ beL,
    const float* __restrict__ c1H, const float* __restrict__ c2H,
    const float* __restrict__ wH,  const float* __restrict__ bH,
    const float* __restrict__ vH,  const float* __restrict__ gH,
    const float* __restrict__ beH,
    const float* __restrict__ alpha, float* __restrict__ out)
{
    __shared__ SMU sm;
    __shared__ unsigned s_dt;
    int bid = blockIdx.x, tid = threadIdx.x;

    if (tid == 0) s_dt = *(volatile unsigned*)&g_done_gen + 1u;   // replay-safe target

    // ================= Phase A: stream X once; H (complete) + G partials ====
    {
        int group = bid >> 3, cb = bid & 7;
        int b = group >> 1, ch = group & 1;
        int cbase = cb * 16;
        const float4* X4 = (const float4*)(ch ? XH : XL);
        const float* c1 = ch ? c1H : c1L;
        const float* c2 = ch ? c2H : c2L;

        for (int t = tid; t < N_; t += 256)
            sm.a.sc2[t] = make_float4(c2[t], c2[N_+t], c2[2*N_+t], c2[3*N_+t]);
        if (tid < 16){
            int c = cbase + tid;
            sm.a.sc1h[tid] = make_float4(c1[c], c1[C_+c], c1[2*C_+c], c1[3*C_+c]);
        }

        int cl = tid / 12, s12 = tid - cl*12;
        bool act = (tid < 192);
        float h0=0.f, h1=0.f, h2=0.f, h3=0.f;

        size_t xbase = (size_t)(b*C_ + cbase) * E4;
        float* g0p = g_Gpart + GPidx(cb,ch,0,b);
        float* g1p = g_Gpart + GPidx(cb,ch,1,b);
        float* g2p = g_Gpart + GPidx(cb,ch,2,b);
        float* g3p = g_Gpart + GPidx(cb,ch,3,b);

        for (int nk = 0; nk < 9; nk++)
            chunkA<32>(sm, X4, xbase, nk, tid, cl, s12, act, h0,h1,h2,h3, g0p,g1p,g2p,g3p);
        chunkA<19>(sm, X4, xbase, 9, tid, cl, s12, act, h0,h1,h2,h3, g0p,g1p,g2p,g3p);

        if (act){
            int c = cbase + cl, sl = s12 + ch;    // logical s (high shifted)
            g_H[Hidx(ch,0,b,sl,c)] = h0;
            g_H[Hidx(ch,1,b,sl,c)] = h1;
            g_H[Hidx(ch,2,b,sl,c)] = h2;
            g_H[Hidx(ch,3,b,sl,c)] = h3;
        }
        if (ch && tid < 16){
            #pragma unroll
            for (int i = 0; i < 4; i++)
                g_H[Hidx(1,i,b,0,cbase + tid)] = 0.f;  // left-pad row
        }
    }
    barrier_n(&g_barA_count, &g_barA_gen, NBLOCKS, true);

    // ================= Phase B: GW_i[b,s,c] = sum_n G_i[b,s,n] * w_i[n,c] ===
    {
        int half = bid & 1;
        int b  = (bid >> 1) & 31;
        int i  = (bid >> 6) & 3;
        int ch =  bid >> 8;
        int nstart = half ? 154 : 0;
        int ncnt   = half ? 153 : 154;
        int e0 = nstart*12, ecnt = ncnt*12;

        for (int j = tid; j < ecnt; j += 256){
            float v = 0.f;
            #pragma unroll
            for (int cb = 0; cb < 8; cb++)
                v += __ldcs(&g_Gpart[GPidx(cb,ch,i,b) + e0 + j]);   // read-once
            sm.b.sg[j] = v;
        }
        __syncthreads();

        int c  = tid & 127;
        int nh = tid >> 7;
        const float* w = (ch ? wH : wL) + (size_t)i*N_*C_;
        float acc[12];
        #pragma unroll
        for (int s = 0; s < 12; s++) acc[s] = 0.f;
        int nmid = ncnt >> 1;
        int nA = nh ? nmid : 0;
        int nB = nh ? ncnt : nmid;
        for (int nl = nA; nl < nB; nl++){
            float wv = __ldg(w + (size_t)(nstart + nl)*C_ + c);
            #pragma unroll
            for (int s = 0; s < 12; s++)
                acc[s] = fmaf(sm.b.sg[nl*12 + s], wv, acc[s]);
        }
        if (nh){
            #pragma unroll
            for (int s = 0; s < 12; s++) sm.b.red[s*128 + c] = acc[s];
        }
        __syncthreads();
        if (!nh){
            int base = GWPidx(half,ch,i,b);
            #pragma unroll
            for (int s = 0; s < 12; s++){
                float v = acc[s] + sm.b.red[s*128 + c];
                g_GWpart[base + (s + ch)*C_ + c] = v;
            }
            if (ch) g_GWpart[base + c] = 0.f;     // logical s=0 pad row
        }
    }
    barrier_n(&g_barA_count, &g_barA_gen, NBLOCKS, true);

    // ================= Phase C: 4-layer chain (64 blocks); others prefetch ==
    if (bid < NCHAIN){
        int ch = bid & 1, b = bid >> 1;
        int T  = ch ? TH : TL;
        const float* bias = ch ? bH  : bL;
        const float* vvp  = ch ? vH  : vL;
        const float* gam  = ch ? gH  : gL;
        const float* bet  = ch ? beH : beL;

        if (tid < T*T){
            int s = tid / T, t = tid % T;
            sm.c.A[s*TMAX + t] = (s == t) ? 1.f : 0.f;
        }
        __syncthreads();

        for (int i = 0; i < LAYERS; i++){
            int hb = Hidx(ch,i,b,0,0);
            int g0 = GWPidx(0,ch,i,b), g1 = GWPidx(1,ch,i,b);
            for (int o = tid; o < T*C_; o += 256){
                int s = o / C_, c = o - s*C_;
                sm.c.GWs[s*PADC + c] = g_GWpart[g0 + o] + g_GWpart[g1 + o];
                sm.c.Hs [s*PADC + c] = g_H[hb + o];
            }
            __syncthreads();

            // f1w[t,c] = sum_s A[s,t]*GW[s,c]; f2[q,c] = sum_s A[s,q]*H[s,c]
            for (int o = tid; o < T*C_; o += 256){
                int t = o / C_, c = o - t*C_;
                float a1 = 0.f, a2 = 0.f;
                for (int s = 0; s < T; s++){
                    float a = sm.c.A[s*TMAX + t];
                    a1 = fmaf(a, sm.c.GWs[s*PADC + c], a1);
                    a2 = fmaf(a, sm.c.Hs [s*PADC + c], a2);
                }
                sm.c.f1w[t*PADC + c] = a1;
                sm.c.f2s[t*PADC + c] = a2;
            }
            __syncthreads();

            // scores[t,q] = sigmoid(f1w . f2 + bias)
            for (int o = tid; o < T*T; o += 256){
                int t = o / T, q = o - t*T;
                float acc = bias[(i*T + t)*T + q];
                for (int c = 0; c < C_; c++)
                    acc = fmaf(sm.c.f1w[t*PADC + c], sm.c.f2s[q*PADC + c], acc);
                sm.c.sS[t*TMAX + q] = 1.f / (1.f + __expf(-acc));
            }
            __syncthreads();

            // logits[t,q] = sum_k v[t,k]*scores[k,q]
            int buf = i & 1;
            for (int o = tid; o < T*T; o += 256){
                int t = o / T, q = o - t*T;
                float acc = 0.f;
                for (int k = 0; k < T; k++)
                    acc = fmaf(vvp[(i*T + t)*T + k], sm.c.sS[k*TMAX + q], acc);
                sm.c.slog[t*TMAX + q] = acc;
                g_logits[buf][((ch*B_ + b)*TMAX + t)*TMAX + q] = acc;
            }
            barrier_n(&g_bar64_count, &g_bar64_gen, NCHAIN, false);

            // BN stats per q over (all b, t) — redundant per block
            {
                int w = tid / 32, lane = tid % 32;
                for (int q = w; q < T; q += 8){
                    float sum = 0.f, sq = 0.f;
                    for (int j = lane; j < B_*T; j += 32){
                        int bb = j / T, t = j - bb*T;
                        float val = __ldcg(&g_logits[buf][((ch*B_ + bb)*TMAX + t)*TMAX + q]);
                        sum += val; sq += val*val;
                    }
                    #pragma unroll
                    for (int off = 16; off; off >>= 1){
                        sum += __shfl_down_sync(0xffffffff, sum, off);
                        sq  += __shfl_down_sync(0xffffffff, sq,  off);
                    }
                    if (lane == 0){
                        float cnt = (float)(B_*T);
                        float m = sum / cnt;
                        float var = sq / cnt - m*m;
                        sm.c.mu[q]  = m;
                        sm.c.isd[q] = rsqrtf(var + BN_EPS);
                    }
                }
            }
            __syncthreads();

            // normalize + softmax over q
            if (tid < T){
                int t = tid;
                float z[TMAX];
                float mx = -1e30f;
                for (int q = 0; q < T; q++){
                    float val = (sm.c.slog[t*TMAX + q] - sm.c.mu[q]) * sm.c.isd[q]
                                * gam[i*T + q] + bet[i*T + q];
                    z[q] = val;
                    mx = fmaxf(mx, val);
                }
                float sum = 0.f;
                for (int q = 0; q < T; q++){ z[q] = __expf(z[q] - mx); sum += z[q]; }
                float inv = 1.f / sum;
                for (int q = 0; q < T; q++) sm.c.sS[t*TMAX + q] = z[q] * inv;
            }
            __syncthreads();

            // A_new[s,q] = sum_t A[s,t] * S[q,t]
            for (int o = tid; o < T*T; o += 256){
                int s = o / T, q = o - s*T;
                float acc = 0.f;
                for (int t = 0; t < T; t++)
                    acc = fmaf(sm.c.A[s*TMAX + t], sm.c.sS[q*TMAX + t], acc);
                sm.c.A2[s*TMAX + q] = acc;
            }
            __syncthreads();
            for (int o = tid; o < T*T; o += 256)
                sm.c.A[(o/T)*TMAX + (o%T)] = sm.c.A2[(o/T)*TMAX + (o%T)];
            __syncthreads();
        }
        if (tid < T)
            g_avec[(ch*B_ + b)*TMAX + tid] = sm.c.A[tid*TMAX + (T-1)];

        barrier_n(&g_bar64_count, &g_bar64_gen, NCHAIN, false);
        if (bid == 0 && tid == 0){
            __threadfence();
            *(volatile unsigned*)&g_done_gen = s_dt;
        }
    } else {
        // idle blocks: prefetch X into L2 for phase D, then wait for flag
        __syncthreads();
        {
            int pb = bid - NCHAIN;                     // 0..447
            const size_t PFB = 56u*1024u*1024u;        // bytes per array to prefetch
            const size_t per = PFB / (NBLOCKS - NCHAIN); // 131072 B per block
            size_t base = (size_t)pb * per;
            const char* pL = (const char*)XL + base;
            const char* pH = (const char*)XH + base;
            for (size_t off = (size_t)tid * 128; off < per; off += 256u*128u){
                asm volatile("prefetch.global.L2 [%0];" :: "l"(pL + off));
                asm volatile("prefetch.global.L2 [%0];" :: "l"(pH + off));
            }
        }
        if (tid == 0){
            volatile unsigned* dg = (volatile unsigned*)&g_done_gen;
            unsigned tgt = s_dt;
            while (*dg != tgt) __nanosleep(64);
            __threadfence();
        }
        __syncthreads();
    }

    // ================= Phase D: residual + alpha mix, streaming, all blocks =
    {
        for (int o = tid; o < 2*B_*TMAX; o += 256) sm.d.av[o] = g_avec[o];
        __syncthreads();

        float sa = 1.f / (1.f + expf(-alpha[0]));
        float sb = 1.f - sa;
        const int total = B_*C_*N_;
        for (int r = bid*256 + tid; r < total; r += NBLOCKS*256){
            int b = r / (C_*N_);
            const float4* xl4 = (const float4*)(XL + (size_t)r*TL);
            const float4* xh4 = (const float4*)(XH + (size_t)r*TL);
            float4 l0 = xl4[0], l1 = xl4[1], l2 = xl4[2];
            float4 h0 = xh4[0], h1 = xh4[1], h2 = xh4[2];
            const float* aL = &sm.d.av[b*TMAX];
            const float* aH = &sm.d.av[(B_ + b)*TMAX];

            float accL = l2.w;
            accL = fmaf(l0.x, aL[0],  accL);
            accL = fmaf(l0.y, aL[1],  accL);
            accL = fmaf(l0.z, aL[2],  accL);
            accL = fmaf(l0.w, aL[3],  accL);
            accL = fmaf(l1.x, aL[4],  accL);
            accL = fmaf(l1.y, aL[5],  accL);
            accL = fmaf(l1.z, aL[6],  accL);
            accL = fmaf(l1.w, aL[7],  accL);
            accL = fmaf(l2.x, aL[8],  accL);
            accL = fmaf(l2.y, aL[9],  accL);
            accL = fmaf(l2.z, aL[10], accL);
            accL = fmaf(l2.w, aL[11], accL);

            float accH = h2.w;
            accH = fmaf(h0.x, aH[1],  accH);
            accH = fmaf(h0.y, aH[2],  accH);
            accH = fmaf(h0.z, aH[3],  accH);
            accH = fmaf(h0.w, aH[4],  accH);
            accH = fmaf(h1.x, aH[5],  accH);
            accH = fmaf(h1.y, aH[6],  accH);
            accH = fmaf(h1.z, aH[7],  accH);
            accH = fmaf(h1.w, aH[8],  accH);
            accH = fmaf(h2.x, aH[9],  accH);
            accH = fmaf(h2.y, aH[10], accH);
            accH = fmaf(h2.z, aH[11], accH);
            accH = fmaf(h2.w, aH[12], accH);

            out[r] = sa*accL + sb*accH;
        }
    }
}

// ---------------- launch ----------------------------------------------------
extern "C" void kernel_launch(void* const* d_in, const int* in_sizes, int n_in,
                              void* d_out, int out_size)
{
    const float* XL  = (const float*)d_in[0];
    const float* XH  = (const float*)d_in[1];
    const float* lc1 = (const float*)d_in[2];
    const float* lc2 = (const float*)d_in[3];
    const float* lw  = (const float*)d_in[4];
    const float* lb  = (const float*)d_in[5];
    const float* lv  = (const float*)d_in[6];
    const float* lg  = (const float*)d_in[7];
    const float* lbe = (const float*)d_in[8];
    const float* hc1 = (const float*)d_in[9];
    const float* hc2 = (const float*)d_in[10];
    const float* hw  = (const float*)d_in[11];
    const float* hb  = (const float*)d_in[12];
    const float* hv  = (const float*)d_in[13];
    const float* hg  = (const float*)d_in[14];
    const float* hbe = (const float*)d_in[15];
    const float* alpha = (const float*)d_in[16];
    float* out = (float*)d_out;

    mega_kernel<<<NBLOCKS, 256>>>(XL, XH,
        lc1, lc2, lw, lb, lv, lg, lbe,
        hc1, hc2, hw, hb, hv, hg, hbe,
        alpha, out);
}

// round 7
// speedup vs baseline: 1.3436x; 1.3436x over previous
#include <cuda_runtime.h>
#include <math.h>

#define B_ 32
#define C_ 128
#define N_ 307
#define TL 12
#define TH 13
#define TMAX 13
#define LAYERS 4
#define BN_EPS 1e-5f
#define E4 921            // float4 per (b,c) row  (307*12/4)
#define EF 3684           // floats per (b,c) row
#define NBLOCKS 512
#define NCHAIN 64
#define NTILE 8
#define PADC 132
#define SSROW 476

// ---------------- scratch (static __device__, no allocations) ----------------
__device__ float g_G [2*4*B_*EF];                // (ch,layer,b,e) complete, 3.8 MB
__device__ float g_Hpart[NTILE*2*4*B_*TMAX*C_];  // (nt,ch,layer,b,sl,c) 13.6 MB
__device__ float g_GWpart[2*2*4*B_*TMAX*C_];     // (half,ch,layer,b,sl,c)
__device__ float g_logits[2][2*B_*TMAX*TMAX];    // double buffered per layer parity
__device__ float g_avec[2*B_*TMAX];              // final A column per (ch,b)
__device__ unsigned g_barA_count, g_barA_gen;    // all-512 barrier
__device__ unsigned g_bar64_count, g_bar64_gen;  // chain-block barrier
__device__ unsigned g_done_gen;                  // chain-done generation flag

__device__ __forceinline__ int Hidx(int ch,int i,int b,int s,int c){
    return (((ch*4+i)*B_+b)*TMAX+s)*C_+c;
}
__device__ __forceinline__ int HPidx(int nt,int ch,int i,int b){
    return ((((nt*2+ch)*4+i)*B_)+b)*TMAX*C_;
}
__device__ __forceinline__ int GWPidx(int half,int ch,int i,int b){
    return (((half*2+ch)*4+i)*B_+b)*TMAX*C_;
}

__device__ __forceinline__ void barrier_n(unsigned* cnt, unsigned* gen, unsigned n, bool sleep){
    __threadfence();
    __syncthreads();
    if (threadIdx.x == 0){
        volatile unsigned* genp = (volatile unsigned*)gen;
        unsigned g = *genp;
        if (atomicAdd(cnt, 1u) == n - 1u){
            atomicExch(cnt, 0u);
            __threadfence();
            *genp = g + 1u;
        } else {
            if (sleep){ while (*genp == g) __nanosleep(32); }
            else      { while (*genp == g) {} }
        }
    }
    __syncthreads();
}

struct SMa { float ss[16][SSROW]; float4 sc2[39]; float4 sc1[C_]; };
struct SMb { float sg[1856]; float red[1536]; };
struct SMc { float A[TMAX*TMAX], A2[TMAX*TMAX];
             float GWs[TMAX*PADC], Hs[TMAX*PADC], f1w[TMAX*PADC], f2s[TMAX*PADC];
             float sS[TMAX*TMAX], slog[TMAX*TMAX], mu[TMAX], isd[TMAX]; };
struct SMd { float av[2*B_*TMAX]; };
union SMU { SMa a; SMb b; SMc c; SMd d; };

// ---- phase A body, compile-time SPAN (39 for tiles 0..2, 38 for 3..7) -------
template<int SPAN>
__device__ __forceinline__ void phaseA(
    SMU& sm, const float4* __restrict__ X4,
    const float* __restrict__ c1, const float* __restrict__ c2,
    int b, int ch, int nt, int n0, int tid)
{
    if (tid < C_)
        sm.a.sc1[tid] = make_float4(c1[tid], c1[C_+tid], c1[2*C_+tid], c1[3*C_+tid]);
    if (tid >= C_ && tid < C_ + SPAN){
        int nl = tid - C_;
        int n = n0 + nl;
        sm.a.sc2[nl] = make_float4(c2[n], c2[N_+n], c2[2*N_+n], c2[3*N_+n]);
    }

    const int pairs = SPAN*12;
    int cl = tid / 12, s12 = tid - cl*12;
    bool actH = (tid < 192);
    int p1 = tid + 256;
    bool act1 = (p1 < pairs);

    float ga0[4], ga1[4];
    #pragma unroll
    for (int i = 0; i < 4; i++){ ga0[i] = 0.f; ga1[i] = 0.f; }

    size_t bc = (size_t)b * C_;
    int hp0 = HPidx(nt,ch,0,b), hp1 = HPidx(nt,ch,1,b);
    int hp2 = HPidx(nt,ch,2,b), hp3 = HPidx(nt,ch,3,b);
    int slH = s12 + ch;

    for (int chunk = 0; chunk < 8; chunk++){
        __syncthreads();
        // stage [16 c][SPAN n][12 s] as contiguous float4 rows
        const int NF4 = SPAN*3;            // float4 per c-row
        #pragma unroll
        for (int j0 = 0; j0 < 16*NF4; j0 += 256){
            int j = j0 + tid;
            if (j < 16*NF4){
                int c = j / NF4, r = j - c*NF4;   // compile-time divisor
                *(float4*)&sm.a.ss[c][r*4] =
                    X4[(bc + chunk*16 + c)*E4 + n0*3 + r];
            }
        }
        __syncthreads();

        // G: accumulate this chunk's 16 c into persistent per-(n,s) registers
        {
            #pragma unroll
            for (int cc = 0; cc < 16; cc++){
                float4 w = sm.a.sc1[chunk*16 + cc];
                float v0 = sm.a.ss[cc][tid];
                ga0[0] = fmaf(w.x, v0, ga0[0]);
                ga0[1] = fmaf(w.y, v0, ga0[1]);
                ga0[2] = fmaf(w.z, v0, ga0[2]);
                ga0[3] = fmaf(w.w, v0, ga0[3]);
                if (act1){
                    float v1 = sm.a.ss[cc][p1];
                    ga1[0] = fmaf(w.x, v1, ga1[0]);
                    ga1[1] = fmaf(w.y, v1, ga1[1]);
                    ga1[2] = fmaf(w.z, v1, ga1[2]);
                    ga1[3] = fmaf(w.w, v1, ga1[3]);
                }
            }
        }

        // H: complete n-reduction for this chunk's 16 c; thread per (c_local,s)
        if (actH){
            float h0=0.f, h1=0.f, h2=0.f, h3=0.f;
            #pragma unroll
            for (int nl = 0; nl < SPAN; nl++){
                float  v = sm.a.ss[cl][nl*12 + s12];
                float4 w = sm.a.sc2[nl];
                h0 = fmaf(w.x, v, h0);
                h1 = fmaf(w.y, v, h1);
                h2 = fmaf(w.z, v, h2);
                h3 = fmaf(w.w, v, h3);
            }
            int c = chunk*16 + cl;
            g_Hpart[hp0 + slH*C_ + c] = h0;
            g_Hpart[hp1 + slH*C_ + c] = h1;
            g_Hpart[hp2 + slH*C_ + c] = h2;
            g_Hpart[hp3 + slH*C_ + c] = h3;
        }
    }

    // write complete G for this n-range (e-flat: e = n*12 + s)
    {
        int e = n0*12 + tid;
        #pragma unroll
        for (int i = 0; i < 4; i++){
            float* gp = g_G + (size_t)((ch*4+i)*B_ + b)*EF;
            gp[e] = ga0[i];
            if (act1) gp[e + 256] = ga1[i];
        }
    }
    // high channel: zero the logical s=0 pad row of Hpart
    if (ch && tid < C_){
        g_Hpart[hp0 + tid] = 0.f;
        g_Hpart[hp1 + tid] = 0.f;
        g_Hpart[hp2 + tid] = 0.f;
        g_Hpart[hp3 + tid] = 0.f;
    }
}

__global__ void __launch_bounds__(256, 4) mega_kernel(
    const float* __restrict__ XL,  const float* __restrict__ XH,
    const float* __restrict__ c1L, const float* __restrict__ c2L,
    const float* __restrict__ wL,  const float* __restrict__ bL,
    const float* __restrict__ vL,  const float* __restrict__ gL,
    const float* __restrict__ beL,
    const float* __restrict__ c1H, const float* __restrict__ c2H,
    const float* __restrict__ wH,  const float* __restrict__ bH,
    const float* __restrict__ vH,  const float* __restrict__ gH,
    const float* __restrict__ beH,
    const float* __restrict__ alpha, float* __restrict__ out)
{
    __shared__ SMU sm;
    __shared__ unsigned s_dt;
    int bid = blockIdx.x, tid = threadIdx.x;

    if (tid == 0) s_dt = *(volatile unsigned*)&g_done_gen + 1u;   // replay-safe target

    // ================= Phase A: stream X once; complete G + H n-partials ====
    {
        int group = bid >> 3, nt = bid & 7;
        int b = group >> 1, ch = group & 1;
        const float4* X4 = (const float4*)(ch ? XH : XL);
        const float* c1 = ch ? c1H : c1L;
        const float* c2 = ch ? c2H : c2L;
        int n0 = nt*38 + min(nt, 3);          // tiles 0..2 span 39, 3..7 span 38
        if (nt < 3) phaseA<39>(sm, X4, c1, c2, b, ch, nt, n0, tid);
        else        phaseA<38>(sm, X4, c1, c2, b, ch, nt, n0, tid);
    }
    barrier_n(&g_barA_count, &g_barA_gen, NBLOCKS, true);

    // ================= Phase B: GW_i[b,s,c] = sum_n G_i[b,s,n] * w_i[n,c] ===
    {
        int half = bid & 1;
        int b  = (bid >> 1) & 31;
        int i  = (bid >> 6) & 3;
        int ch =  bid >> 8;
        int nstart = half ? 154 : 0;
        int ncnt   = half ? 153 : 154;
        int e0 = nstart*12, ecnt = ncnt*12;

        const float* gp = g_G + (size_t)((ch*4+i)*B_ + b)*EF;
        for (int j = tid; j < ecnt; j += 256)
            sm.b.sg[j] = gp[e0 + j];
        __syncthreads();

        int c  = tid & 127;
        int nh = tid >> 7;
        const float* w = (ch ? wH : wL) + (size_t)i*N_*C_;
        float acc[12];
        #pragma unroll
        for (int s = 0; s < 12; s++) acc[s] = 0.f;
        int nmid = ncnt >> 1;
        int nA = nh ? nmid : 0;
        int nB = nh ? ncnt : nmid;
        for (int nl = nA; nl < nB; nl++){
            float wv = __ldg(w + (size_t)(nstart + nl)*C_ + c);
            #pragma unroll
            for (int s = 0; s < 12; s++)
                acc[s] = fmaf(sm.b.sg[nl*12 + s], wv, acc[s]);
        }
        if (nh){
            #pragma unroll
            for (int s = 0; s < 12; s++) sm.b.red[s*128 + c] = acc[s];
        }
        __syncthreads();
        if (!nh){
            int base = GWPidx(half,ch,i,b);
            #pragma unroll
            for (int s = 0; s < 12; s++){
                float v = acc[s] + sm.b.red[s*128 + c];
                g_GWpart[base + (s + ch)*C_ + c] = v;
            }
            if (ch) g_GWpart[base + c] = 0.f;     // logical s=0 pad row
        }
    }
    barrier_n(&g_barA_count, &g_barA_gen, NBLOCKS, true);

    // ================= Phase C: 4-layer chain (64 blocks); others wait flag =
    if (bid < NCHAIN){
        int ch = bid & 1, b = bid >> 1;
        int T  = ch ? TH : TL;
        const float* bias = ch ? bH  : bL;
        const float* vvp  = ch ? vH  : vL;
        const float* gam  = ch ? gH  : gL;
        const float* bet  = ch ? beH : beL;

        if (tid < T*T){
            int s = tid / T, t = tid % T;
            sm.c.A[s*TMAX + t] = (s == t) ? 1.f : 0.f;
        }
        __syncthreads();

        for (int i = 0; i < LAYERS; i++){
            int g0 = GWPidx(0,ch,i,b), g1 = GWPidx(1,ch,i,b);
            int hp[NTILE];
            #pragma unroll
            for (int nt = 0; nt < NTILE; nt++) hp[nt] = HPidx(nt,ch,i,b);
            for (int o = tid; o < T*C_; o += 256){
                int s = o / C_, c = o - s*C_;
                sm.c.GWs[s*PADC + c] = g_GWpart[g0 + o] + g_GWpart[g1 + o];
                float h = 0.f;
                #pragma unroll
                for (int nt = 0; nt < NTILE; nt++) h += g_Hpart[hp[nt] + o];
                sm.c.Hs[s*PADC + c] = h;
            }
            __syncthreads();

            // f1w[t,c] = sum_s A[s,t]*GW[s,c]; f2[q,c] = sum_s A[s,q]*H[s,c]
            for (int o = tid; o < T*C_; o += 256){
                int t = o / C_, c = o - t*C_;
                float a1 = 0.f, a2 = 0.f;
                for (int s = 0; s < T; s++){
                    float a = sm.c.A[s*TMAX + t];
                    a1 = fmaf(a, sm.c.GWs[s*PADC + c], a1);
                    a2 = fmaf(a, sm.c.Hs [s*PADC + c], a2);
                }
                sm.c.f1w[t*PADC + c] = a1;
                sm.c.f2s[t*PADC + c] = a2;
            }
            __syncthreads();

            // scores[t,q] = sigmoid(f1w . f2 + bias)
            for (int o = tid; o < T*T; o += 256){
                int t = o / T, q = o - t*T;
                float acc = bias[(i*T + t)*T + q];
                for (int c = 0; c < C_; c++)
                    acc = fmaf(sm.c.f1w[t*PADC + c], sm.c.f2s[q*PADC + c], acc);
                sm.c.sS[t*TMAX + q] = 1.f / (1.f + __expf(-acc));
            }
            __syncthreads();

            // logits[t,q] = sum_k v[t,k]*scores[k,q]
            int buf = i & 1;
            for (int o = tid; o < T*T; o += 256){
                int t = o / T, q = o - t*T;
                float acc = 0.f;
                for (int k = 0; k < T; k++)
                    acc = fmaf(vvp[(i*T + t)*T + k], sm.c.sS[k*TMAX + q], acc);
                sm.c.slog[t*TMAX + q] = acc;
                g_logits[buf][((ch*B_ + b)*TMAX + t)*TMAX + q] = acc;
            }
            barrier_n(&g_bar64_count, &g_bar64_gen, NCHAIN, false);

            // BN stats per q over (all b, t) — redundant per block
            {
                int w = tid / 32, lane = tid % 32;
                for (int q = w; q < T; q += 8){
                    float sum = 0.f, sq = 0.f;
                    for (int j = lane; j < B_*T; j += 32){
                        int bb = j / T, t = j - bb*T;
                        float val = __ldcg(&g_logits[buf][((ch*B_ + bb)*TMAX + t)*TMAX + q]);
                        sum += val; sq += val*val;
                    }
                    #pragma unroll
                    for (int off = 16; off; off >>= 1){
                        sum += __shfl_down_sync(0xffffffff, sum, off);
                        sq  += __shfl_down_sync(0xffffffff, sq,  off);
                    }
                    if (lane == 0){
                        float cnt = (float)(B_*T);
                        float m = sum / cnt;
                        float var = sq / cnt - m*m;
                        sm.c.mu[q]  = m;
                        sm.c.isd[q] = rsqrtf(var + BN_EPS);
                    }
                }
            }
            __syncthreads();

            // normalize + softmax over q
            if (tid < T){
                int t = tid;
                float z[TMAX];
                float mx = -1e30f;
                for (int q = 0; q < T; q++){
                    float val = (sm.c.slog[t*TMAX + q] - sm.c.mu[q]) * sm.c.isd[q]
                                * gam[i*T + q] + bet[i*T + q];
                    z[q] = val;
                    mx = fmaxf(mx, val);
                }
                float sum = 0.f;
                for (int q = 0; q < T; q++){ z[q] = __expf(z[q] - mx); sum += z[q]; }
                float inv = 1.f / sum;
                for (int q = 0; q < T; q++) sm.c.sS[t*TMAX + q] = z[q] * inv;
            }
            __syncthreads();

            // A_new[s,q] = sum_t A[s,t] * S[q,t]
            for (int o = tid; o < T*T; o += 256){
                int s = o / T, q = o - s*T;
                float acc = 0.f;
                for (int t = 0; t < T; t++)
                    acc = fmaf(sm.c.A[s*TMAX + t], sm.c.sS[q*TMAX + t], acc);
                sm.c.A2[s*TMAX + q] = acc;
            }
            __syncthreads();
            for (int o = tid; o < T*T; o += 256)
                sm.c.A[(o/T)*TMAX + (o%T)] = sm.c.A2[(o/T)*TMAX + (o%T)];
            __syncthreads();
        }
        if (tid < T)
            g_avec[(ch*B_ + b)*TMAX + tid] = sm.c.A[tid*TMAX + (T-1)];

        barrier_n(&g_bar64_count, &g_bar64_gen, NCHAIN, false);
        if (bid == 0 && tid == 0){
            __threadfence();
            *(volatile unsigned*)&g_done_gen = s_dt;
        }
    } else {
        // idle blocks: wait for chain completion flag
        __syncthreads();
        if (tid == 0){
            volatile unsigned* dg = (volatile unsigned*)&g_done_gen;
            unsigned tgt = s_dt;
            while (*dg != tgt) __nanosleep(64);
            __threadfence();
        }
        __syncthreads();
    }

    // ================= Phase D: residual + alpha mix, streaming, all blocks =
    {
        for (int o = tid; o < 2*B_*TMAX; o += 256) sm.d.av[o] = g_avec[o];
        __syncthreads();

        float sa = 1.f / (1.f + expf(-alpha[0]));
        float sb = 1.f - sa;
        const int total = B_*C_*N_;
        for (int r = bid*256 + tid; r < total; r += NBLOCKS*256){
            int b = r / (C_*N_);
            const float4* xl4 = (const float4*)(XL + (size_t)r*TL);
            const float4* xh4 = (const float4*)(XH + (size_t)r*TL);
            float4 l0 = xl4[0], l1 = xl4[1], l2 = xl4[2];
            float4 h0 = xh4[0], h1 = xh4[1], h2 = xh4[2];
            const float* aL = &sm.d.av[b*TMAX];
            const float* aH = &sm.d.av[(B_ + b)*TMAX];

            float accL = l2.w;
            accL = fmaf(l0.x, aL[0],  accL);
            accL = fmaf(l0.y, aL[1],  accL);
            accL = fmaf(l0.z, aL[2],  accL);
            accL = fmaf(l0.w, aL[3],  accL);
            accL = fmaf(l1.x, aL[4],  accL);
            accL = fmaf(l1.y, aL[5],  accL);
            accL = fmaf(l1.z, aL[6],  accL);
            accL = fmaf(l1.w, aL[7],  accL);
            accL = fmaf(l2.x, aL[8],  accL);
            accL = fmaf(l2.y, aL[9],  accL);
            accL = fmaf(l2.z, aL[10], accL);
            accL = fmaf(l2.w, aL[11], accL);

            float accH = h2.w;
            accH = fmaf(h0.x, aH[1],  accH);
            accH = fmaf(h0.y, aH[2],  accH);
            accH = fmaf(h0.z, aH[3],  accH);
            accH = fmaf(h0.w, aH[4],  accH);
            accH = fmaf(h1.x, aH[5],  accH);
            accH = fmaf(h1.y, aH[6],  accH);
            accH = fmaf(h1.z, aH[7],  accH);
            accH = fmaf(h1.w, aH[8],  accH);
            accH = fmaf(h2.x, aH[9],  accH);
            accH = fmaf(h2.y, aH[10], accH);
            accH = fmaf(h2.z, aH[11], accH);
            accH = fmaf(h2.w, aH[12], accH);

            out[r] = sa*accL + sb*accH;
        }
    }
}

// ---------------- launch ----------------------------------------------------
extern "C" void kernel_launch(void* const* d_in, const int* in_sizes, int n_in,
                              void* d_out, int out_size)
{
    const float* XL  = (const float*)d_in[0];
    const float* XH  = (const float*)d_in[1];
    const float* lc1 = (const float*)d_in[2];
    const float* lc2 = (const float*)d_in[3];
    const float* lw  = (const float*)d_in[4];
    const float* lb  = (const float*)d_in[5];
    const float* lv  = (const float*)d_in[6];
    const float* lg  = (const float*)d_in[7];
    const float* lbe = (const float*)d_in[8];
    const float* hc1 = (const float*)d_in[9];
    const float* hc2 = (const float*)d_in[10];
    const float* hw  = (const float*)d_in[11];
    const float* hb  = (const float*)d_in[12];
    const float* hv  = (const float*)d_in[13];
    const float* hg  = (const float*)d_in[14];
    const float* hbe = (const float*)d_in[15];
    const float* alpha = (const float*)d_in[16];
    float* out = (float*)d_out;

    mega_kernel<<<NBLOCKS, 256>>>(XL, XH,
        lc1, lc2, lw, lb, lv, lg, lbe,
        hc1, hc2, hw, hb, hv, hg, hbe,
        alpha, out);
}

// round 8
// speedup vs baseline: 1.4152x; 1.0533x over previous
#include <cuda_runtime.h>
#include <math.h>

#define B_ 32
#define C_ 128
#define N_ 307
#define TL 12
#define TH 13
#define TMAX 13
#define LAYERS 4
#define BN_EPS 1e-5f
#define E4 921            // float4 per (b,c) row  (307*12/4)
#define EF 3684           // floats per (b,c) row
#define NBLOCKS 512
#define NCHAIN 64
#define NTILE 8
#define PADC 132
#define SSROW2 492        // floats per staged c-row (>= 39*12=468; %32=12; *4B %16=0)

// ---------------- scratch (static __device__, no allocations) ----------------
__device__ float g_G [2*4*B_*EF];                // (ch,layer,b,e) complete, 3.8 MB
__device__ float g_Hpart[NTILE*2*4*B_*TMAX*C_];  // (nt,ch,layer,b,sl,c) 13.6 MB
__device__ float g_GWpart[2*2*4*B_*TMAX*C_];     // (half,ch,layer,b,sl,c)
__device__ float g_logits[2][2*B_*TMAX*TMAX];    // double buffered per layer parity
__device__ float g_avec[2*B_*TMAX];              // final A column per (ch,b)
__device__ unsigned g_barA_count, g_barA_gen;    // all-512 barrier
__device__ unsigned g_bar64_count, g_bar64_gen;  // chain-block barrier
__device__ unsigned g_done_gen;                  // chain-done generation flag

__device__ __forceinline__ int HPidx(int nt,int ch,int i,int b){
    return ((((nt*2+ch)*4+i)*B_)+b)*TMAX*C_;
}
__device__ __forceinline__ int GWPidx(int half,int ch,int i,int b){
    return (((half*2+ch)*4+i)*B_+b)*TMAX*C_;
}

__device__ __forceinline__ void barrier_n(unsigned* cnt, unsigned* gen, unsigned n, bool sleep){
    __threadfence();
    __syncthreads();
    if (threadIdx.x == 0){
        volatile unsigned* genp = (volatile unsigned*)gen;
        unsigned g = *genp;
        if (atomicAdd(cnt, 1u) == n - 1u){
            atomicExch(cnt, 0u);
            __threadfence();
            *genp = g + 1u;
        } else {
            if (sleep){ while (*genp == g) __nanosleep(32); }
            else      { while (*genp == g) {} }
        }
    }
    __syncthreads();
}

struct __align__(16) SMa { float ss[2][8][SSROW2]; float4 sc2[39]; float4 sc1[C_]; float hred[96*4]; };
struct SMb { float sg[1856]; float red[1536]; };
struct SMc { float A[TMAX*TMAX], A2[TMAX*TMAX];
             float GWs[TMAX*PADC], Hs[TMAX*PADC], f1w[TMAX*PADC], f2s[TMAX*PADC];
             float sS[TMAX*TMAX], slog[TMAX*TMAX], mu[TMAX], isd[TMAX]; };
struct SMd { float av[2*B_*TMAX]; };
union SMU { SMa a; SMb b; SMc c; SMd d; };

// ---- phase A: cp.async double-buffered; compile-time SPAN (39 / 38) ---------
template<int SPAN>
__device__ __forceinline__ void phaseA(
    SMU& sm, const float4* __restrict__ X4,
    const float* __restrict__ c1, const float* __restrict__ c2,
    int b, int ch, int nt, int n0, int tid)
{
    const int NF4 = SPAN*3;          // float4 per c-row
    const int TOT = 8*NF4;           // float4 per chunk (8 channels)
    const int H1  = SPAN/2;          // lower-half n count

    if (tid < C_)
        sm.a.sc1[tid] = make_float4(c1[tid], c1[C_+tid], c1[2*C_+tid], c1[3*C_+tid]);
    if (tid >= C_ && tid < C_ + SPAN){
        int nl = tid - C_;
        int n = n0 + nl;
        sm.a.sc2[nl] = make_float4(c2[n], c2[N_+n], c2[2*N_+n], c2[3*N_+n]);
    }

    const int pairs = SPAN*12;
    int hh  = tid / 96;                      // 0: lower n-half, 1: upper (tid<192)
    int rem = tid - hh*96;
    int cl  = rem / 12, s12 = rem - cl*12;
    bool actH = (tid < 192);
    int p1 = tid + 256;
    bool act1 = (p1 < pairs);

    float ga0[4], ga1[4];
    #pragma unroll
    for (int i = 0; i < 4; i++){ ga0[i] = 0.f; ga1[i] = 0.f; }

    size_t bc = (size_t)b * C_;
    int hp0 = HPidx(nt,ch,0,b), hp1 = HPidx(nt,ch,1,b);
    int hp2 = HPidx(nt,ch,2,b), hp3 = HPidx(nt,ch,3,b);
    int slH = s12 + ch;

    // issue one 8-channel chunk into buffer (chunk&1) via cp.async
    auto issue = [&](int chunk){
        int bufi = chunk & 1;
        #pragma unroll
        for (int j0 = 0; j0 < TOT; j0 += 256){
            int j = j0 + tid;
            if (j < TOT){
                int c = j / NF4, r = j - c*NF4;
                const void* src = (const void*)&X4[(bc + (size_t)(chunk*8 + c))*E4 + n0*3 + r];
                unsigned dst = (unsigned)__cvta_generic_to_shared(&sm.a.ss[bufi][c][r*4]);
                asm volatile("cp.async.cg.shared.global [%0], [%1], 16;" :: "r"(dst), "l"(src));
            }
        }
        asm volatile("cp.async.commit_group;" ::: "memory");
    };

    issue(0);
    for (int chunk = 0; chunk < 16; chunk++){
        if (chunk < 15){
            issue(chunk + 1);
            asm volatile("cp.async.wait_group 1;" ::: "memory");
        } else {
            asm volatile("cp.async.wait_group 0;" ::: "memory");
        }
        __syncthreads();                                     // S1: chunk data ready
        const float* bufp = &sm.a.ss[chunk & 1][0][0];

        // G: accumulate this chunk's 8 channels into persistent regs
        #pragma unroll
        for (int cc = 0; cc < 8; cc++){
            float4 w = sm.a.sc1[chunk*8 + cc];
            float v0 = bufp[cc*SSROW2 + tid];
            ga0[0] = fmaf(w.x, v0, ga0[0]);
            ga0[1] = fmaf(w.y, v0, ga0[1]);
            ga0[2] = fmaf(w.z, v0, ga0[2]);
            ga0[3] = fmaf(w.w, v0, ga0[3]);
            if (act1){
                float v1 = bufp[cc*SSROW2 + p1];
                ga1[0] = fmaf(w.x, v1, ga1[0]);
                ga1[1] = fmaf(w.y, v1, ga1[1]);
                ga1[2] = fmaf(w.z, v1, ga1[2]);
                ga1[3] = fmaf(w.w, v1, ga1[3]);
            }
        }

        // H: per-chunk n-reduction split across two thread-halves
        float h0 = 0.f, h1 = 0.f, h2 = 0.f, h3 = 0.f;
        if (actH){
            const float* row = bufp + cl*SSROW2 + s12;
            if (hh){
                #pragma unroll
                for (int nl = H1; nl < SPAN; nl++){
                    float  v = row[nl*12];
                    float4 w = sm.a.sc2[nl];
                    h0 = fmaf(w.x, v, h0);
                    h1 = fmaf(w.y, v, h1);
                    h2 = fmaf(w.z, v, h2);
                    h3 = fmaf(w.w, v, h3);
                }
                sm.a.hred[rem*4+0] = h0;
                sm.a.hred[rem*4+1] = h1;
                sm.a.hred[rem*4+2] = h2;
                sm.a.hred[rem*4+3] = h3;
            } else {
                #pragma unroll
                for (int nl = 0; nl < H1; nl++){
                    float  v = row[nl*12];
                    float4 w = sm.a.sc2[nl];
                    h0 = fmaf(w.x, v, h0);
                    h1 = fmaf(w.y, v, h1);
                    h2 = fmaf(w.z, v, h2);
                    h3 = fmaf(w.w, v, h3);
                }
            }
        }
        __syncthreads();                                     // S2: buf free, hred visible
        if (actH && !hh){
            int c = chunk*8 + cl;
            g_Hpart[hp0 + slH*C_ + c] = h0 + sm.a.hred[rem*4+0];
            g_Hpart[hp1 + slH*C_ + c] = h1 + sm.a.hred[rem*4+1];
            g_Hpart[hp2 + slH*C_ + c] = h2 + sm.a.hred[rem*4+2];
            g_Hpart[hp3 + slH*C_ + c] = h3 + sm.a.hred[rem*4+3];
        }
    }

    // write complete G for this n-range (e-flat: e = n*12 + s)
    {
        int e = n0*12 + tid;
        #pragma unroll
        for (int i = 0; i < 4; i++){
            float* gp = g_G + (size_t)((ch*4+i)*B_ + b)*EF;
            gp[e] = ga0[i];
            if (act1) gp[e + 256] = ga1[i];
        }
    }
    // high channel: zero the logical s=0 pad row of Hpart
    if (ch && tid < C_){
        g_Hpart[hp0 + tid] = 0.f;
        g_Hpart[hp1 + tid] = 0.f;
        g_Hpart[hp2 + tid] = 0.f;
        g_Hpart[hp3 + tid] = 0.f;
    }
}

__global__ void __launch_bounds__(256, 4) mega_kernel(
    const float* __restrict__ XL,  const float* __restrict__ XH,
    const float* __restrict__ c1L, const float* __restrict__ c2L,
    const float* __restrict__ wL,  const float* __restrict__ bL,
    const float* __restrict__ vL,  const float* __restrict__ gL,
    const float* __restrict__ beL,
    const float* __restrict__ c1H, const float* __restrict__ c2H,
    const float* __restrict__ wH,  const float* __restrict__ bH,
    const float* __restrict__ vH,  const float* __restrict__ gH,
    const float* __restrict__ beH,
    const float* __restrict__ alpha, float* __restrict__ out)
{
    __shared__ SMU sm;
    __shared__ unsigned s_dt;
    int bid = blockIdx.x, tid = threadIdx.x;

    if (tid == 0) s_dt = *(volatile unsigned*)&g_done_gen + 1u;   // replay-safe target

    // ================= Phase A: stream X once; complete G + H n-partials ====
    {
        int group = bid >> 3, nt = bid & 7;
        int b = group >> 1, ch = group & 1;
        const float4* X4 = (const float4*)(ch ? XH : XL);
        const float* c1 = ch ? c1H : c1L;
        const float* c2 = ch ? c2H : c2L;
        int n0 = nt*38 + min(nt, 3);          // tiles 0..2 span 39, 3..7 span 38
        if (nt < 3) phaseA<39>(sm, X4, c1, c2, b, ch, nt, n0, tid);
        else        phaseA<38>(sm, X4, c1, c2, b, ch, nt, n0, tid);
    }
    barrier_n(&g_barA_count, &g_barA_gen, NBLOCKS, true);

    // ================= Phase B: GW_i[b,s,c] = sum_n G_i[b,s,n] * w_i[n,c] ===
    {
        int half = bid & 1;
        int b  = (bid >> 1) & 31;
        int i  = (bid >> 6) & 3;
        int ch =  bid >> 8;
        int nstart = half ? 154 : 0;
        int ncnt   = half ? 153 : 154;
        int e0 = nstart*12, ecnt = ncnt*12;

        const float* gp = g_G + (size_t)((ch*4+i)*B_ + b)*EF;
        for (int j = tid; j < ecnt; j += 256)
            sm.b.sg[j] = gp[e0 + j];
        __syncthreads();

        int c  = tid & 127;
        int nh = tid >> 7;
        const float* w = (ch ? wH : wL) + (size_t)i*N_*C_;
        float acc[12];
        #pragma unroll
        for (int s = 0; s < 12; s++) acc[s] = 0.f;
        int nmid = ncnt >> 1;
        int nA = nh ? nmid : 0;
        int nB = nh ? ncnt : nmid;
        for (int nl = nA; nl < nB; nl++){
            float wv = __ldg(w + (size_t)(nstart + nl)*C_ + c);
            #pragma unroll
            for (int s = 0; s < 12; s++)
                acc[s] = fmaf(sm.b.sg[nl*12 + s], wv, acc[s]);
        }
        if (nh){
            #pragma unroll
            for (int s = 0; s < 12; s++) sm.b.red[s*128 + c] = acc[s];
        }
        __syncthreads();
        if (!nh){
            int base = GWPidx(half,ch,i,b);
            #pragma unroll
            for (int s = 0; s < 12; s++){
                float v = acc[s] + sm.b.red[s*128 + c];
                g_GWpart[base + (s + ch)*C_ + c] = v;
            }
            if (ch) g_GWpart[base + c] = 0.f;     // logical s=0 pad row
        }
    }
    barrier_n(&g_barA_count, &g_barA_gen, NBLOCKS, true);

    // ================= Phase C: 4-layer chain (64 blocks); others wait flag =
    if (bid < NCHAIN){
        int ch = bid & 1, b = bid >> 1;
        int T  = ch ? TH : TL;
        const float* bias = ch ? bH  : bL;
        const float* vvp  = ch ? vH  : vL;
        const float* gam  = ch ? gH  : gL;
        const float* bet  = ch ? beH : beL;

        if (tid < T*T){
            int s = tid / T, t = tid % T;
            sm.c.A[s*TMAX + t] = (s == t) ? 1.f : 0.f;
        }
        __syncthreads();

        for (int i = 0; i < LAYERS; i++){
            int g0 = GWPidx(0,ch,i,b), g1 = GWPidx(1,ch,i,b);
            int hp[NTILE];
            #pragma unroll
            for (int nt = 0; nt < NTILE; nt++) hp[nt] = HPidx(nt,ch,i,b);
            for (int o = tid; o < T*C_; o += 256){
                int s = o / C_, c = o - s*C_;
                sm.c.GWs[s*PADC + c] = g_GWpart[g0 + o] + g_GWpart[g1 + o];
                float h = 0.f;
                #pragma unroll
                for (int nt = 0; nt < NTILE; nt++) h += g_Hpart[hp[nt] + o];
                sm.c.Hs[s*PADC + c] = h;
            }
            __syncthreads();

            // f1w[t,c] = sum_s A[s,t]*GW[s,c]; f2[q,c] = sum_s A[s,q]*H[s,c]
            for (int o = tid; o < T*C_; o += 256){
                int t = o / C_, c = o - t*C_;
                float a1 = 0.f, a2 = 0.f;
                for (int s = 0; s < T; s++){
                    float a = sm.c.A[s*TMAX + t];
                    a1 = fmaf(a, sm.c.GWs[s*PADC + c], a1);
                    a2 = fmaf(a, sm.c.Hs [s*PADC + c], a2);
                }
                sm.c.f1w[t*PADC + c] = a1;
                sm.c.f2s[t*PADC + c] = a2;
            }
            __syncthreads();

            // scores[t,q] = sigmoid(f1w . f2 + bias)
            for (int o = tid; o < T*T; o += 256){
                int t = o / T, q = o - t*T;
                float acc = bias[(i*T + t)*T + q];
                for (int c = 0; c < C_; c++)
                    acc = fmaf(sm.c.f1w[t*PADC + c], sm.c.f2s[q*PADC + c], acc);
                sm.c.sS[t*TMAX + q] = 1.f / (1.f + __expf(-acc));
            }
            __syncthreads();

            // logits[t,q] = sum_k v[t,k]*scores[k,q]
            int buf = i & 1;
            for (int o = tid; o < T*T; o += 256){
                int t = o / T, q = o - t*T;
                float acc = 0.f;
                for (int k = 0; k < T; k++)
                    acc = fmaf(vvp[(i*T + t)*T + k], sm.c.sS[k*TMAX + q], acc);
                sm.c.slog[t*TMAX + q] = acc;
                g_logits[buf][((ch*B_ + b)*TMAX + t)*TMAX + q] = acc;
            }
            barrier_n(&g_bar64_count, &g_bar64_gen, NCHAIN, false);

            // BN stats per q over (all b, t) — redundant per block
            {
                int w = tid / 32, lane = tid % 32;
                for (int q = w; q < T; q += 8){
                    float sum = 0.f, sq = 0.f;
                    for (int j = lane; j < B_*T; j += 32){
                        int bb = j / T, t = j - bb*T;
                        float val = __ldcg(&g_logits[buf][((ch*B_ + bb)*TMAX + t)*TMAX + q]);
                        sum += val; sq += val*val;
                    }
                    #pragma unroll
                    for (int off = 16; off; off >>= 1){
                        sum += __shfl_down_sync(0xffffffff, sum, off);
                        sq  += __shfl_down_sync(0xffffffff, sq,  off);
                    }
                    if (lane == 0){
                        float cnt = (float)(B_*T);
                        float m = sum / cnt;
                        float var = sq / cnt - m*m;
                        sm.c.mu[q]  = m;
                        sm.c.isd[q] = rsqrtf(var + BN_EPS);
                    }
                }
            }
            __syncthreads();

            // normalize + softmax over q
            if (tid < T){
                int t = tid;
                float z[TMAX];
                float mx = -1e30f;
                for (int q = 0; q < T; q++){
                    float val = (sm.c.slog[t*TMAX + q] - sm.c.mu[q]) * sm.c.isd[q]
                                * gam[i*T + q] + bet[i*T + q];
                    z[q] = val;
                    mx = fmaxf(mx, val);
                }
                float sum = 0.f;
                for (int q = 0; q < T; q++){ z[q] = __expf(z[q] - mx); sum += z[q]; }
                float inv = 1.f / sum;
                for (int q = 0; q < T; q++) sm.c.sS[t*TMAX + q] = z[q] * inv;
            }
            __syncthreads();

            // A_new[s,q] = sum_t A[s,t] * S[q,t]
            for (int o = tid; o < T*T; o += 256){
                int s = o / T, q = o - s*T;
                float acc = 0.f;
                for (int t = 0; t < T; t++)
                    acc = fmaf(sm.c.A[s*TMAX + t], sm.c.sS[q*TMAX + t], acc);
                sm.c.A2[s*TMAX + q] = acc;
            }
            __syncthreads();
            for (int o = tid; o < T*T; o += 256)
                sm.c.A[(o/T)*TMAX + (o%T)] = sm.c.A2[(o/T)*TMAX + (o%T)];
            __syncthreads();
        }
        if (tid < T)
            g_avec[(ch*B_ + b)*TMAX + tid] = sm.c.A[tid*TMAX + (T-1)];

        barrier_n(&g_bar64_count, &g_bar64_gen, NCHAIN, false);
        if (bid == 0 && tid == 0){
            __threadfence();
            *(volatile unsigned*)&g_done_gen = s_dt;
        }
    } else {
        // idle blocks: wait for chain completion flag
        __syncthreads();
        if (tid == 0){
            volatile unsigned* dg = (volatile unsigned*)&g_done_gen;
            unsigned tgt = s_dt;
            while (*dg != tgt) __nanosleep(64);
            __threadfence();
        }
        __syncthreads();
    }

    // ================= Phase D: residual + alpha mix, streaming, all blocks =
    {
        for (int o = tid; o < 2*B_*TMAX; o += 256) sm.d.av[o] = g_avec[o];
        __syncthreads();

        float sa = 1.f / (1.f + expf(-alpha[0]));
        float sb = 1.f - sa;
        const int total = B_*C_*N_;
        for (int r = bid*256 + tid; r < total; r += NBLOCKS*256){
            int b = r / (C_*N_);
            const float4* xl4 = (const float4*)(XL + (size_t)r*TL);
            const float4* xh4 = (const float4*)(XH + (size_t)r*TL);
            float4 l0 = xl4[0], l1 = xl4[1], l2 = xl4[2];
            float4 h0 = xh4[0], h1 = xh4[1], h2 = xh4[2];
            const float* aL = &sm.d.av[b*TMAX];
            const float* aH = &sm.d.av[(B_ + b)*TMAX];

            float accL = l2.w;
            accL = fmaf(l0.x, aL[0],  accL);
            accL = fmaf(l0.y, aL[1],  accL);
            accL = fmaf(l0.z, aL[2],  accL);
            accL = fmaf(l0.w, aL[3],  accL);
            accL = fmaf(l1.x, aL[4],  accL);
            accL = fmaf(l1.y, aL[5],  accL);
            accL = fmaf(l1.z, aL[6],  accL);
            accL = fmaf(l1.w, aL[7],  accL);
            accL = fmaf(l2.x, aL[8],  accL);
            accL = fmaf(l2.y, aL[9],  accL);
            accL = fmaf(l2.z, aL[10], accL);
            accL = fmaf(l2.w, aL[11], accL);

            float accH = h2.w;
            accH = fmaf(h0.x, aH[1],  accH);
            accH = fmaf(h0.y, aH[2],  accH);
            accH = fmaf(h0.z, aH[3],  accH);
            accH = fmaf(h0.w, aH[4],  accH);
            accH = fmaf(h1.x, aH[5],  accH);
            accH = fmaf(h1.y, aH[6],  accH);
            accH = fmaf(h1.z, aH[7],  accH);
            accH = fmaf(h1.w, aH[8],  accH);
            accH = fmaf(h2.x, aH[9],  accH);
            accH = fmaf(h2.y, aH[10], accH);
            accH = fmaf(h2.z, aH[11], accH);
            accH = fmaf(h2.w, aH[12], accH);

            out[r] = sa*accL + sb*accH;
        }
    }
}

// ---------------- launch ----------------------------------------------------
extern "C" void kernel_launch(void* const* d_in, const int* in_sizes, int n_in,
                              void* d_out, int out_size)
{
    const float* XL  = (const float*)d_in[0];
    const float* XH  = (const float*)d_in[1];
    const float* lc1 = (const float*)d_in[2];
    const float* lc2 = (const float*)d_in[3];
    const float* lw  = (const float*)d_in[4];
    const float* lb  = (const float*)d_in[5];
    const float* lv  = (const float*)d_in[6];
    const float* lg  = (const float*)d_in[7];
    const float* lbe = (const float*)d_in[8];
    const float* hc1 = (const float*)d_in[9];
    const float* hc2 = (const float*)d_in[10];
    const float* hw  = (const float*)d_in[11];
    const float* hb  = (const float*)d_in[12];
    const float* hv  = (const float*)d_in[13];
    const float* hg  = (const float*)d_in[14];
    const float* hbe = (const float*)d_in[15];
    const float* alpha = (const float*)d_in[16];
    float* out = (float*)d_out;

    mega_kernel<<<NBLOCKS, 256>>>(XL, XH,
        lc1, lc2, lw, lb, lv, lg, lbe,
        hc1, hc2, hw, hb, hv, hg, hbe,
        alpha, out);
}